// round 17
// baseline (speedup 1.0000x reference)
#include <cuda_runtime.h>
#include <cuda_fp16.h>
#include <cstdint>

#define B_  8
#define D_  256
#define T_  2048
#define K_  8192
#define BT_ (B_ * T_)
#define ZQ_ELEMS (BT_ * D_)
#define SLACK 1.5e-3f

// ---------------- device scratch ----------------
__device__ __half g_zhi[BT_ * D_];          // [m][d] fp16 hi of z
__device__ __half g_chi[K_ * D_];           // [n][d] fp16 hi of 512*cb
__device__ __half g_approx[(size_t)BT_ * K_];  // r~ = -2*dot_hh + s2 (256MB)
__device__ float g_s1[BT_];
__device__ float g_s2[K_];
__device__ float g_hz[BT_];                 // ||hi_z|| per row (upper bound)
__device__ float g_lz[BT_];                 // ||lo_z|| per row (upper bound)
__device__ int   g_maxHcBits;               // max_n ||hi_c|| (float bits)
__device__ int   g_maxLcBits;               // max_n ||lo_c|| (float bits)
__device__ unsigned long long g_best[BT_];
__device__ double g_loss;

#define CP16(sa, ga) asm volatile("cp.async.cg.shared.global [%0], [%1], 16;" \
    :: "r"((uint32_t)(sa)), "l"(ga) : "memory")
#define CP_COMMIT()  asm volatile("cp.async.commit_group;" ::: "memory")

__device__ __forceinline__ uint32_t smem_u32(const void* p) {
    uint32_t a;
    asm("{ .reg .u64 t; cvta.to.shared.u64 t, %1; cvt.u32.u64 %0, t; }"
        : "=r"(a) : "l"(p));
    return a;
}

#define LDM4(r, addr) \
    asm volatile("ldmatrix.sync.aligned.m8n8.x4.shared.b16 {%0,%1,%2,%3}, [%4];" \
        : "=r"((r)[0]), "=r"((r)[1]), "=r"((r)[2]), "=r"((r)[3]) : "r"(addr))

// ------- split codebook (x512) -> fp16 hi [K][D], s2, norm maxima -------
__global__ void split_cb_kernel(const float* __restrict__ cb) {
    if (blockIdx.x == 0 && threadIdx.x == 0) g_loss = 0.0;
    int w = threadIdx.x >> 5, lane = threadIdx.x & 31;
    int n = blockIdx.x * 8 + w;
    size_t base = (size_t)n * D_;
    double s = 0.0;
    float hc2 = 0.0f, lc2 = 0.0f;
    const float inv512 = 1.0f / 512.0f;
    #pragma unroll
    for (int i = 0; i < 8; i++) {
        float v = cb[base + lane + 32 * i];
        s += (double)v * v;
        float vs = v * 512.0f;                 // exact
        __half hi = __float2half_rn(vs);
        float hif = __half2float(hi);          // exact
        float lof = vs - hif;                  // exact (Sterbenz-adjacent)
        g_chi[base + lane + 32 * i] = hi;
        float hu = hif * inv512, lu = lof * inv512;   // unscaled magnitudes
        hc2 = __fmaf_rn(hu, hu, hc2);
        lc2 = __fmaf_rn(lu, lu, lc2);
    }
    #pragma unroll
    for (int o = 16; o; o >>= 1) {
        s   += __shfl_xor_sync(0xffffffffu, s, o);
        hc2 += __shfl_xor_sync(0xffffffffu, hc2, o);
        lc2 += __shfl_xor_sync(0xffffffffu, lc2, o);
    }
    if (lane == 0) {
        g_s2[n] = (float)s;
        float hc = sqrtf(hc2) * 1.0002f + 1e-12f;
        float lc = sqrtf(lc2) * 1.0002f + 1e-12f;
        atomicMax(&g_maxHcBits, __float_as_int(hc));
        atomicMax(&g_maxLcBits, __float_as_int(lc));
    }
}

// ------- split z -> fp16 hi [m][d], s1, per-row hi/lo norms -------
__global__ void split_z_kernel(const float* __restrict__ z) {
    __shared__ float  sz[32][257];
    __shared__ double sred[8][33];
    int m0 = blockIdx.x * 32;
    int b  = m0 >> 11;
    int t0 = m0 & 2047;
    int tt = threadIdx.x & 31;
    int dp = threadIdx.x >> 5;
    double s = 0.0;
    #pragma unroll
    for (int di = 0; di < 32; di++) {
        int d = dp * 32 + di;
        float v = z[((size_t)b * D_ + d) * T_ + t0 + tt];
        sz[tt][d] = v;
        s += (double)v * v;
    }
    sred[dp][tt] = s;
    __syncthreads();
    if (dp == 0) {
        double tot = 0.0;
        #pragma unroll
        for (int p = 0; p < 8; p++) tot += sred[p][tt];
        g_s1[m0 + tt] = (float)tot;
    }
    #pragma unroll
    for (int r8 = 0; r8 < 4; r8++) {
        int row = dp * 4 + r8;
        size_t base = (size_t)(m0 + row) * D_;
        float hz2 = 0.0f, lz2 = 0.0f;
        #pragma unroll
        for (int i = 0; i < 8; i++) {
            int d = tt + 32 * i;
            float v  = sz[row][d];
            __half hi = __float2half_rn(v);
            float hif = __half2float(hi);
            float lof = v - hif;
            g_zhi[base + d] = hi;
            hz2 = __fmaf_rn(hif, hif, hz2);
            lz2 = __fmaf_rn(lof, lof, lz2);
        }
        #pragma unroll
        for (int o = 16; o; o >>= 1) {
            hz2 += __shfl_xor_sync(0xffffffffu, hz2, o);
            lz2 += __shfl_xor_sync(0xffffffffu, lz2, o);
        }
        if (tt == 0) {
            g_hz[m0 + row] = sqrtf(hz2) * 1.0002f + 1e-12f;
            g_lz[m0 + row] = sqrtf(lz2) * 1.0002f + 1e-12f;
        }
    }
}

// NOTE: z hi/lo split here is of UNSCALED z; fp16 products hi_z*hi_c are exact
// in fp32 accum. The lo_z residual (v - hif) is exact in fp32.

// -------- phase 1: hi*hi approx GEMM, 3-stage pipeline, store fp16 --------
#define MATB1 8192                    // 128 rows * 64 B
#define STB1  (2 * MATB1)             // A_hi + B_hi per stage
#define NST   3
#define SMEM_BYTES (NST * STB1)       // 49152
#define NCH   8

__device__ __forceinline__ void mma_fp16(float* c, const uint32_t* a,
                                         uint32_t b0, uint32_t b1) {
    asm("mma.sync.aligned.m16n8k16.row.col.f32.f16.f16.f32 "
        "{%0,%1,%2,%3}, {%4,%5,%6,%7}, {%8,%9}, {%0,%1,%2,%3};"
        : "+f"(c[0]), "+f"(c[1]), "+f"(c[2]), "+f"(c[3])
        : "r"(a[0]), "r"(a[1]), "r"(a[2]), "r"(a[3]), "r"(b0), "r"(b1));
}

__global__ void __launch_bounds__(256, 2)
dist_approx_kernel() {
    extern __shared__ char smem[];
    uint32_t sbase = smem_u32(smem);

    int tid  = threadIdx.x;
    int wid  = tid >> 5, lane = tid & 31;
    int g    = lane >> 2;
    int tig  = lane & 3;
    int wm   = wid >> 1;       // 0..3
    int wn   = wid & 1;        // 0..1
    int m0   = blockIdx.y * 128;
    int n0   = blockIdx.x * 128;

    // ldmatrix swizzled per-lane offsets (64B rows, unit q at ((q^((r>>1)&3))<<4))
    int aRow = (lane & 7) + ((lane >> 3) & 1) * 8;
    int u0A  = lane >> 4;
    int swA  = (aRow >> 1) & 3;
    int bRow = (lane & 7) + (lane >> 4) * 8;
    int ub0  = (lane >> 3) & 1;
    int swB  = (bRow >> 1) & 3;
    uint32_t offA_k[2], offB_k[2];
    offA_k[0] = (uint32_t)((wm * 32 + aRow) * 64 + (((u0A + 0) ^ swA) << 4));
    offA_k[1] = (uint32_t)((wm * 32 + aRow) * 64 + (((u0A + 2) ^ swA) << 4));
    offB_k[0] = (uint32_t)((wn * 64 + bRow) * 64 + (((ub0 + 0) ^ swB) << 4));
    offB_k[1] = (uint32_t)((wn * 64 + bRow) * 64 + (((ub0 + 2) ^ swB) << 4));

    // cp.async swizzled offsets
    int srow = tid >> 1;
    int swS  = (srow >> 1) & 3;
    int q0 = (tid & 1) * 2;
    uint32_t so0 = (uint32_t)(srow * 64 + (((q0 + 0) ^ swS) << 4));
    uint32_t so1 = (uint32_t)(srow * 64 + (((q0 + 1) ^ swS) << 4));
    const __half* pA = g_zhi + (size_t)(m0 + srow) * D_ + q0 * 8;
    const __half* pB = g_chi + (size_t)(n0 + srow) * D_ + q0 * 8;

    float acc[2][8][4];
    #pragma unroll
    for (int mt = 0; mt < 2; mt++)
        #pragma unroll
        for (int nt = 0; nt < 8; nt++)
            #pragma unroll
            for (int q = 0; q < 4; q++) acc[mt][nt][q] = 0.0f;

    #define ISSUE_CHUNK(it2, stg) do {                                       \
        uint32_t s0 = sbase + (stg) * STB1;                                   \
        ptrdiff_t dd = (ptrdiff_t)((it2) * 32);                               \
        CP16(s0 + so0,         pA + dd);                                      \
        CP16(s0 + so1,         pA + dd + 8);                                  \
        CP16(s0 + MATB1 + so0, pB + dd);                                      \
        CP16(s0 + MATB1 + so1, pB + dd + 8);                                  \
        CP_COMMIT();                                                          \
    } while (0)

    ISSUE_CHUNK(0, 0);
    ISSUE_CHUNK(1, 1);

    int stC = 0, stI = 2;
    for (int it = 0; it < NCH; it++) {
        if (it < NCH - 1) asm volatile("cp.async.wait_group 1;" ::: "memory");
        else              asm volatile("cp.async.wait_group 0;" ::: "memory");
        __syncthreads();
        if (it + 2 < NCH) ISSUE_CHUNK(it + 2, stI);

        uint32_t mAh = sbase + (uint32_t)stC * STB1;
        uint32_t mBh = mAh + MATB1;

        #pragma unroll
        for (int kh = 0; kh < 2; kh++) {
            uint32_t oA = offA_k[kh], oB = offB_k[kh];
            uint32_t ah[2][4], bb[4][4];
            #pragma unroll
            for (int p = 0; p < 4; p++)
                LDM4(bb[p], mBh + oB + (uint32_t)(p * 1024));
            LDM4(ah[0], mAh + oA);
            LDM4(ah[1], mAh + oA + 1024);
            #pragma unroll
            for (int p = 0; p < 4; p++) {
                mma_fp16(acc[0][2 * p],     ah[0], bb[p][0], bb[p][1]);
                mma_fp16(acc[1][2 * p],     ah[1], bb[p][0], bb[p][1]);
                mma_fp16(acc[0][2 * p + 1], ah[0], bb[p][2], bb[p][3]);
                mma_fp16(acc[1][2 * p + 1], ah[1], bb[p][2], bb[p][3]);
            }
        }
        stC = (stC == 2) ? 0 : stC + 1;
        stI = (stI == 2) ? 0 : stI + 1;
    }

    // ----- epilogue: store r~ = fma(-2/512, acc, s2) as fp16 -----
    #pragma unroll
    for (int mt = 0; mt < 2; mt++) {
        int row0 = m0 + wm * 32 + mt * 16 + g;
        int row1 = row0 + 8;
        #pragma unroll
        for (int nt = 0; nt < 8; nt++) {
            int nb = n0 + wn * 64 + nt * 8 + 2 * tig;
            float2 s2p = *reinterpret_cast<const float2*>(g_s2 + nb);
            float v0 = __fmaf_rn(-0.00390625f, acc[mt][nt][0], s2p.x);
            float v1 = __fmaf_rn(-0.00390625f, acc[mt][nt][1], s2p.y);
            float v2 = __fmaf_rn(-0.00390625f, acc[mt][nt][2], s2p.x);
            float v3 = __fmaf_rn(-0.00390625f, acc[mt][nt][3], s2p.y);
            *reinterpret_cast<__half2*>(&g_approx[(size_t)row0 * K_ + nb]) =
                __floats2half2_rn(v0, v1);
            *reinterpret_cast<__half2*>(&g_approx[(size_t)row1 * K_ + nb]) =
                __floats2half2_rn(v2, v3);
        }
    }
}

// -------- phase 2: scan row, window candidates, exact fp64 refine --------
__global__ void __launch_bounds__(128)
refine_kernel(const float* __restrict__ z, const float* __restrict__ cb) {
    __shared__ float sredf[4];
    __shared__ unsigned long long skeys[128];
    int m = blockIdx.x;
    int tid = threadIdx.x;
    int lane = tid & 31, wid = tid >> 5;

    const uint4* row = reinterpret_cast<const uint4*>(g_approx + (size_t)m * K_);
    uint4 v[8];
    #pragma unroll
    for (int j = 0; j < 8; j++) v[j] = row[tid + 128 * j];

    // min over 64 halves (hmin2 tree)
    __half2 m2 = *reinterpret_cast<__half2*>(&v[0].x);
    #pragma unroll
    for (int j = 0; j < 8; j++) {
        const __half2* h = reinterpret_cast<const __half2*>(&v[j]);
        #pragma unroll
        for (int p = (j == 0 ? 1 : 0); p < 4; p++) m2 = __hmin2(m2, h[p]);
    }
    float fm = fminf(__low2float(m2), __high2float(m2));
    #pragma unroll
    for (int o = 16; o; o >>= 1)
        fm = fminf(fm, __shfl_xor_sync(0xffffffffu, fm, o));
    if (lane == 0) sredf[wid] = fm;
    __syncthreads();
    float fmin = fminf(fminf(sredf[0], sredf[1]), fminf(sredf[2], sredf[3]));

    // sound window
    float hz = g_hz[m], lz = g_lz[m];
    float Hc = __int_as_float(g_maxHcBits);
    float Lc = __int_as_float(g_maxLcBits);
    float W  = 4.0f * (hz * Lc + lz * Hc + lz * Lc) + SLACK;
    float thr = fmin + W;

    float s1f = g_s1[m];
    int b = m >> 11, t0 = m & 2047;
    const float* zr = z + (size_t)b * D_ * T_ + t0;

    unsigned long long best = 0xFFFFFFFFFFFFFFFFULL;
    #pragma unroll
    for (int j = 0; j < 8; j++) {
        const __half2* h = reinterpret_cast<const __half2*>(&v[j]);
        #pragma unroll
        for (int p = 0; p < 4; p++) {
            float2 f2 = __half22float2(h[p]);
            #pragma unroll
            for (int e = 0; e < 2; e++) {
                float hv = (e == 0) ? f2.x : f2.y;
                if (hv <= thr) {
                    int n = (tid + 128 * j) * 8 + p * 2 + e;
                    const float* cr = cb + (size_t)n * D_;
                    double dot = 0.0;
                    for (int d = 0; d < D_; d += 8) {
                        #pragma unroll
                        for (int q = 0; q < 8; q++)
                            dot += (double)__ldg(zr + (size_t)(d + q) * T_) *
                                   (double)__ldg(cr + d + q);
                    }
                    float df = (float)dot;
                    float f = __fmaf_rn(-2.0f, df, s1f) + __ldg(&g_s2[n]);
                    unsigned u = __float_as_uint(f);
                    u = (u & 0x80000000u) ? ~u : (u | 0x80000000u);
                    unsigned long long key =
                        ((unsigned long long)u << 32) | (unsigned)n;
                    best = best < key ? best : key;
                }
            }
        }
    }
    skeys[tid] = best;
    __syncthreads();
    #pragma unroll
    for (int s = 64; s; s >>= 1) {
        if (tid < s) {
            unsigned long long o = skeys[tid + s];
            if (o < skeys[tid]) skeys[tid] = o;
        }
        __syncthreads();
    }
    if (tid == 0) g_best[m] = skeys[0];
}

// ---------------- gather z_q_st, indices, loss ----------------
__global__ void gather_kernel(const float* __restrict__ z,
                              const float* __restrict__ cb,
                              float* __restrict__ out, int out_size) {
    __shared__ float sm[32][257];
    __shared__ int   sidx[32];
    __shared__ double ssum[8];
    int m0 = blockIdx.x * 32;
    int b  = m0 >> 11;
    int t0 = m0 & 2047;
    int tid = threadIdx.x;

    if (tid < 32) {
        int idx = (int)(g_best[m0 + tid] & 0xFFFFFFFFULL);
        sidx[tid] = idx;
        if (out_size >= ZQ_ELEMS + BT_)
            out[ZQ_ELEMS + m0 + tid] = (float)idx;
    }
    __syncthreads();
    #pragma unroll
    for (int r = 0; r < 32; r++)
        sm[r][tid] = cb[(size_t)sidx[r] * D_ + tid];
    __syncthreads();

    int tt = tid & 31, dp = tid >> 5;
    double lsum = 0.0;
    #pragma unroll 4
    for (int it = 0; it < 32; it++) {
        int d = dp * 32 + it;
        size_t oi = ((size_t)b * D_ + d) * T_ + t0 + tt;
        float zq = sm[tt][d];
        float zv = z[oi];
        float r  = zq - zv;
        out[oi]  = zv + r;
        lsum += (double)r * r;
    }
    #pragma unroll
    for (int o = 16; o; o >>= 1) lsum += __shfl_xor_sync(0xffffffffu, lsum, o);
    if (tt == 0) ssum[dp] = lsum;
    __syncthreads();
    if (tid == 0) {
        double tot = 0.0;
        #pragma unroll
        for (int p = 0; p < 8; p++) tot += ssum[p];
        atomicAdd(&g_loss, tot);
    }
}

__global__ void finalize_kernel(float* __restrict__ out, int out_size) {
    if (out_size >= ZQ_ELEMS + BT_ + 1)
        out[ZQ_ELEMS + BT_] = (float)(1.1 * g_loss / (double)ZQ_ELEMS);
}

// ---------------- launch ----------------
extern "C" void kernel_launch(void* const* d_in, const int* in_sizes, int n_in,
                              void* d_out, int out_size) {
    const float* z  = (const float*)d_in[0];
    const float* cb = (const float*)d_in[1];
    if (n_in >= 2 && in_sizes[0] == K_ * D_ && in_sizes[1] == ZQ_ELEMS) {
        const float* t = z; z = cb; cb = t;
    }
    float* out = (float*)d_out;

    cudaFuncSetAttribute(dist_approx_kernel,
                         cudaFuncAttributeMaxDynamicSharedMemorySize, SMEM_BYTES);

    split_cb_kernel<<<K_ / 8, 256>>>(cb);
    split_z_kernel<<<BT_ / 32, 256>>>(z);

    dim3 grid(K_ / 128, BT_ / 128);   // (64, 128)
    dist_approx_kernel<<<grid, 256, SMEM_BYTES>>>();

    refine_kernel<<<BT_, 128>>>(z, cb);

    gather_kernel<<<BT_ / 32, 256>>>(z, cb, out, out_size);
    finalize_kernel<<<1, 1>>>(out, out_size);
}